// round 1
// baseline (speedup 1.0000x reference)
#include <cuda_runtime.h>
#include <cuda_bf16.h>
#include <cstdint>

// Problem constants (fixed by the dataset)
#define NN 50000
#define NE 1600000
#define NB 4
#define NT 50
#define FDT 0.02f

// ---------------- device scratch (static, no allocations) ----------------
__device__ float2 g_csr[NE];            // per edge: {weight, bitcast(src)} sorted by target
__device__ int    g_row_start[NN + 1];  // CSR row offsets (by target)
__device__ int    g_deg[NN];
__device__ int    g_cursor[NN];
__device__ float  g_v[2][NN * 4];       // ping-pong state, layout [node][batch]

// ---------------- prep kernels ----------------
__global__ void init_kernel(const float* __restrict__ bias) {
    int i = blockIdx.x * blockDim.x + threadIdx.x;
    if (i < NN) {
        g_deg[i] = 0;
        g_cursor[i] = 0;
        float b = bias[i];
        float4 v = make_float4(b, b, b, b);
        *reinterpret_cast<float4*>(&g_v[0][4 * i]) = v;
    }
}

__global__ void hist_kernel(const int* __restrict__ tgt) {
    int i = blockIdx.x * blockDim.x + threadIdx.x;
    if (i < NE) atomicAdd(&g_deg[tgt[i]], 1);
}

// Single-block exclusive scan over g_deg -> g_row_start  (50k elems, tiny)
__global__ void scan_kernel() {
    __shared__ int warp_sums[32];
    __shared__ int s_carry;
    const int tid = threadIdx.x;
    const int lane = tid & 31, wid = tid >> 5;
    if (tid == 0) s_carry = 0;
    __syncthreads();
    for (int base = 0; base < NN; base += 1024) {
        int i = base + tid;
        int v = (i < NN) ? g_deg[i] : 0;
        int x = v;
        #pragma unroll
        for (int o = 1; o < 32; o <<= 1) {
            int y = __shfl_up_sync(0xffffffffu, x, o);
            if (lane >= o) x += y;
        }
        if (lane == 31) warp_sums[wid] = x;
        __syncthreads();
        if (wid == 0) {
            int w = warp_sums[lane];
            #pragma unroll
            for (int o = 1; o < 32; o <<= 1) {
                int y = __shfl_up_sync(0xffffffffu, w, o);
                if (lane >= o) w += y;
            }
            warp_sums[lane] = w;
        }
        __syncthreads();
        int warp_off = (wid == 0) ? 0 : warp_sums[wid - 1];
        int incl = x + warp_off;
        int carry = s_carry;                    // read before update below
        if (i < NN) g_row_start[i] = carry + incl - v;   // exclusive
        __syncthreads();
        if (tid == 1023) s_carry = carry + incl;         // chunk total
        __syncthreads();
    }
    if (tid == 0) g_row_start[NN] = s_carry;
}

__global__ void scatter_kernel(const int* __restrict__ src, const int* __restrict__ tgt,
                               const float* __restrict__ sign, const float* __restrict__ cnt,
                               const float* __restrict__ strg) {
    int i = blockIdx.x * blockDim.x + threadIdx.x;
    if (i >= NE) return;
    float w = sign[i] * fmaxf(cnt[i], 0.0f) * fmaxf(strg[i], 0.0f);
    int t = tgt[i];
    int pos = atomicAdd(&g_cursor[t], 1);
    g_csr[g_row_start[t] + pos] = make_float2(w, __int_as_float(src[i]));
}

// ---------------- main step: warp-per-row CSR SpMM + Euler update ----------------
__global__ void __launch_bounds__(256) step_kernel(const float* __restrict__ bias,
                                                   const float* __restrict__ tc,
                                                   const float* __restrict__ x,
                                                   float* __restrict__ out,
                                                   int t, int parity) {
    const float* __restrict__ v_old = g_v[parity];
    float* __restrict__ v_new = g_v[parity ^ 1];

    int warp = blockIdx.x * (blockDim.x >> 5) + (threadIdx.x >> 5);
    int lane = threadIdx.x & 31;
    if (warp >= NN) return;
    const int row = warp;
    const int s = __ldg(&g_row_start[row]);
    const int e = __ldg(&g_row_start[row + 1]);

    float ax = 0.f, ay = 0.f, az = 0.f, aw = 0.f;
    for (int i = s + lane; i < e; i += 32) {
        float2 p = __ldcs(&g_csr[i]);             // streaming: keep L1 for v_old
        int srcn = __float_as_int(p.y);
        float w = p.x;
        float4 r = *reinterpret_cast<const float4*>(v_old + 4 * srcn);
        ax += fmaxf(r.x, 0.f) * w;
        ay += fmaxf(r.y, 0.f) * w;
        az += fmaxf(r.z, 0.f) * w;
        aw += fmaxf(r.w, 0.f) * w;
    }
    #pragma unroll
    for (int o = 16; o; o >>= 1) {
        ax += __shfl_down_sync(0xffffffffu, ax, o);
        ay += __shfl_down_sync(0xffffffffu, ay, o);
        az += __shfl_down_sync(0xffffffffu, az, o);
        aw += __shfl_down_sync(0xffffffffu, aw, o);
    }
    if (lane == 0) {
        float b_ = __ldg(&bias[row]);
        float alpha = FDT / fmaxf(__ldg(&tc[row]), FDT);
        float sums[4] = {ax, ay, az, aw};
        float4 vo4 = *reinterpret_cast<const float4*>(v_old + 4 * row);
        float vo[4] = {vo4.x, vo4.y, vo4.z, vo4.w};
        float vn[4];
        #pragma unroll
        for (int b = 0; b < 4; b++) {
            float xv = __ldcs(&x[(b * NT + t) * NN + row]);
            vn[b] = vo[b] + alpha * (b_ - vo[b] + sums[b] + xv);
            out[(b * NT + t) * NN + row] = fmaxf(vn[b], 0.f);
        }
        *reinterpret_cast<float4*>(v_new + 4 * row) =
            make_float4(vn[0], vn[1], vn[2], vn[3]);
    }
}

// ---------------- launch ----------------
extern "C" void kernel_launch(void* const* d_in, const int* in_sizes, int n_in,
                              void* d_out, int out_size) {
    const float* x      = (const float*)d_in[0];  // [B,T,N]
    const float* bias   = (const float*)d_in[1];  // [N]
    const float* tcst   = (const float*)d_in[2];  // [N]
    const float* sign   = (const float*)d_in[3];  // [E]
    const float* cnt    = (const float*)d_in[4];  // [E]
    const float* strg   = (const float*)d_in[5];  // [E]
    const int*   srcidx = (const int*)d_in[6];    // [E]
    const int*   tgtidx = (const int*)d_in[7];    // [E]
    float* out = (float*)d_out;                   // [B,T,N]

    const int nblk = (NN + 255) / 256;
    const int eblk = (NE + 255) / 256;

    init_kernel<<<nblk, 256>>>(bias);
    hist_kernel<<<eblk, 256>>>(tgtidx);
    scan_kernel<<<1, 1024>>>();
    scatter_kernel<<<eblk, 256>>>(srcidx, tgtidx, sign, cnt, strg);

    // warp per row: 8 rows per 256-thread block
    const int sblk = (NN + 7) / 8;
    for (int t = 0; t < NT; t++) {
        step_kernel<<<sblk, 256>>>(bias, tcst, x, out, t, t & 1);
    }
    (void)in_sizes; (void)n_in; (void)out_size;
}